// round 3
// baseline (speedup 1.0000x reference)
#include <cuda_runtime.h>
#include <math.h>

#define B_   2
#define CIN  32
#define COUT 32
#define D_   40
#define E_   3
#define SP   (D_*D_*D_)          // 64000
#define YTOT (B_*COUT*SP)        // 4,096,000
#define TZ   4
#define NZT  (D_/TZ)             // 10
#define SLABZ (TZ+2)
#define SY   42
#define WPB  (CIN*27)            // 864 weights per (b,oc)

// ---- scratch (device globals; no runtime allocation) ----
__device__ float g_w[B_*COUT*CIN*27];   // combined conv weights per sample
__device__ float g_bias[B_*COUT];
__device__ float g_y[YTOT];             // pre-upsample activations (16.4 MB)
__device__ float g_sum[COUT];
__device__ float g_sumsq[COUT];
__device__ float g_scale[COUT];
__device__ float g_shift[COUT];

// ---------------------------------------------------------------------------
// Kernel 1: routing + combined weights/bias, zero stat accumulators
// ---------------------------------------------------------------------------
__global__ void k_route(const float* __restrict__ emb,
                        const float* __restrict__ rw,
                        const float* __restrict__ rb,
                        const float* __restrict__ ek,
                        const float* __restrict__ eb) {
    // per-thread recompute of routing (EMB == 1): 6 sigmoids, trivial
    float r[B_][E_];
    #pragma unroll
    for (int b = 0; b < B_; b++)
        #pragma unroll
        for (int e = 0; e < E_; e++) {
            float t = fmaf(emb[b], rw[e], rb[e]);
            r[b][e] = 1.0f / (1.0f + expf(-t));
        }

    int idx = blockIdx.x * blockDim.x + threadIdx.x;
    const int W = COUT * CIN * 27;                 // 27648 per batch
    if (idx < B_ * W) {
        int b = idx / W;
        int w = idx - b * W;
        float s = 0.0f;
        #pragma unroll
        for (int e = 0; e < E_; e++) s = fmaf(r[b][e], ek[e * W + w], s);
        g_w[idx] = s;
    }
    if (idx < B_ * COUT) {
        int b = idx / COUT, o = idx - b * COUT;
        float s = 0.0f;
        #pragma unroll
        for (int e = 0; e < E_; e++) s = fmaf(r[b][e], eb[e * COUT + o], s);
        g_bias[idx] = s;
    }
    if (idx < COUT) { g_sum[idx] = 0.0f; g_sumsq[idx] = 0.0f; }
}

// ---------------------------------------------------------------------------
// Kernel 2: direct 3x3x3 conv (cross-correlation, SAME) + bias + BN stats
// grid = (z-tiles=10, oc=32, b=2), block = 224 threads (200 compute)
// each compute thread: 4(z) x 8(x) register accumulator tile at fixed y
// ---------------------------------------------------------------------------
__global__ void __launch_bounds__(224)
k_conv(const float* __restrict__ x) {
    __shared__ float sh[SLABZ][SY][SY];   // 6*42*42 floats = 42.3 KB
    __shared__ float wsh[WPB];            // 864 floats
    __shared__ float red[16];

    const int zt = blockIdx.x;            // 0..9
    const int oc = blockIdx.y;            // 0..31
    const int b  = blockIdx.z;            // 0..1
    const int t  = threadIdx.x;
    const int z0 = zt * TZ;

    // weights for this (b, oc): all 32 ic x 27 taps
    for (int i = t; i < WPB; i += 224)
        wsh[i] = g_w[(b * COUT + oc) * WPB + i];

    const int ty = t / 5;                 // 0..39 (y row)
    const int xs = (t % 5) * 8;           // x start: 0,8,16,24,32
    const bool active = (t < 200);

    float acc[TZ][8];
    #pragma unroll
    for (int z = 0; z < TZ; z++)
        #pragma unroll
        for (int j = 0; j < 8; j++) acc[z][j] = 0.0f;

    const float* xb = x + (size_t)(b * CIN) * SP;

    for (int ic = 0; ic < CIN; ic++) {
        __syncthreads();   // previous compute done (and weights visible on ic=0)
        // cooperative slab load with zero halo: z in [z0-1, z0+4], y,x in [-1,40]
        const float* xc = xb + (size_t)ic * SP;
        for (int s = t; s < SLABZ * SY * SY; s += 224) {
            int zz = s / (SY * SY);
            int rem = s - zz * (SY * SY);
            int yy = rem / SY;
            int xx = rem - yy * SY;
            int gz = z0 - 1 + zz, gy = yy - 1, gx = xx - 1;
            float v = 0.0f;
            if ((unsigned)gz < D_ && (unsigned)gy < D_ && (unsigned)gx < D_)
                v = xc[gz * 1600 + gy * 40 + gx];
            ((float*)sh)[s] = v;
        }
        __syncthreads();

        if (active) {
            const float* wv = &wsh[ic * 27];
            #pragma unroll
            for (int zz = 0; zz < SLABZ; zz++) {
                #pragma unroll
                for (int ky = 0; ky < 3; ky++) {
                    float r[10];
                    #pragma unroll
                    for (int i = 0; i < 10; i++) r[i] = sh[zz][ty + ky][xs + i];
                    #pragma unroll
                    for (int dz = 0; dz < 3; dz++) {
                        const int z = zz - dz;           // output local z
                        if (z >= 0 && z < TZ) {          // compile-time after unroll
                            #pragma unroll
                            for (int kx = 0; kx < 3; kx++) {
                                float w = wv[dz * 9 + ky * 3 + kx];
                                #pragma unroll
                                for (int j = 0; j < 8; j++)
                                    acc[z][j] = fmaf(w, r[j + kx], acc[z][j]);
                            }
                        }
                    }
                }
            }
        }
    }

    // epilogue: bias, store y, partial BN sums
    float s1 = 0.0f, s2 = 0.0f;
    if (active) {
        const float bias = g_bias[b * COUT + oc];
        float* yp = g_y + (size_t)(b * COUT + oc) * SP + z0 * 1600 + ty * 40 + xs;
        #pragma unroll
        for (int z = 0; z < TZ; z++) {
            #pragma unroll
            for (int j = 0; j < 8; j++) {
                float v = acc[z][j] + bias;
                yp[z * 1600 + j] = v;
                s1 += v;
                s2 = fmaf(v, v, s2);
            }
        }
    }
    // block reduction -> atomic per-channel stats
    #pragma unroll
    for (int o = 16; o > 0; o >>= 1) {
        s1 += __shfl_down_sync(0xffffffff, s1, o);
        s2 += __shfl_down_sync(0xffffffff, s2, o);
    }
    const int wid = t >> 5, lane = t & 31;
    __syncthreads();
    if (lane == 0) { red[wid] = s1; red[8 + wid] = s2; }
    __syncthreads();
    if (t == 0) {
        float a = 0.0f, q = 0.0f;
        #pragma unroll
        for (int i = 0; i < 7; i++) { a += red[i]; q += red[8 + i]; }
        atomicAdd(&g_sum[oc], a);
        atomicAdd(&g_sumsq[oc], q);
    }
}

// ---------------------------------------------------------------------------
// Kernel 3: finalize BN -> per-channel scale/shift
// ---------------------------------------------------------------------------
__global__ void k_stats(const float* __restrict__ gamma,
                        const float* __restrict__ beta) {
    int c = threadIdx.x;
    if (c < COUT) {
        const float n = (float)(B_ * SP);
        float mean = g_sum[c] / n;
        float var  = g_sumsq[c] / n - mean * mean;
        float sc = gamma[c] * rsqrtf(var + 1e-5f);
        g_scale[c] = sc;
        g_shift[c] = beta[c] - mean * sc;
    }
}

// ---------------------------------------------------------------------------
// Kernel 4: affine + LeakyReLU + nearest upsample x2 (each y elem -> 8 out)
// ---------------------------------------------------------------------------
__global__ void __launch_bounds__(256)
k_up(float* __restrict__ out) {
    int idx = blockIdx.x * blockDim.x + threadIdx.x;
    if (idx >= YTOT) return;
    int xw = idx % 40;
    int rest = idx / 40;
    int yw = rest % 40; rest /= 40;
    int zw = rest % 40; rest /= 40;
    int c  = rest % COUT;
    int b  = rest / COUT;

    float v = g_y[idx];
    float a = fmaf(g_scale[c], v, g_shift[c]);
    a = (a >= 0.0f) ? a : 0.1f * a;

    float2 p = make_float2(a, a);
    // out[b][c] is 80^3 = 512000 elems; write 4 float2 (covers 2x2x2 block)
    size_t base = ((size_t)(b * COUT + c) * 512000u)
                + (size_t)(2 * zw) * 6400u + (size_t)(2 * yw) * 80u + (size_t)(2 * xw);
    float2* o = (float2*)out;
    size_t b2 = base >> 1;
    o[b2]        = p;   // (2z, 2y)
    o[b2 + 40]   = p;   // (2z, 2y+1)
    o[b2 + 3200] = p;   // (2z+1, 2y)
    o[b2 + 3240] = p;   // (2z+1, 2y+1)
}

// ---------------------------------------------------------------------------
extern "C" void kernel_launch(void* const* d_in, const int* in_sizes, int n_in,
                              void* d_out, int out_size) {
    const float* x     = (const float*)d_in[0];
    const float* emb   = (const float*)d_in[1];
    const float* rw    = (const float*)d_in[2];
    const float* rb    = (const float*)d_in[3];
    const float* ek    = (const float*)d_in[4];
    const float* eb    = (const float*)d_in[5];
    const float* gamma = (const float*)d_in[6];
    const float* beta  = (const float*)d_in[7];
    float* out = (float*)d_out;

    k_route<<<(B_ * COUT * CIN * 27 + 255) / 256, 256>>>(emb, rw, rb, ek, eb);

    dim3 gconv(NZT, COUT, B_);
    k_conv<<<gconv, 224>>>(x);

    k_stats<<<1, 32>>>(gamma, beta);

    k_up<<<(YTOT + 255) / 256, 256>>>(out);
}

// round 5
// speedup vs baseline: 1.0089x; 1.0089x over previous
#include <cuda_runtime.h>
#include <math.h>

#define B_    2
#define CIN   32
#define COUT  32
#define D_    40
#define E_    3
#define SP    (D_*D_*D_)          // 64000
#define YTOT  (B_*COUT*SP)        // 4,096,000
#define TZ    4
#define NZT   (D_/TZ)             // 10
#define SLABZ (TZ+2)              // 6
#define SY    42
#define SLABVOL (SLABZ*SY*SY)     // 10584
#define WPB   (CIN*27)            // 864

typedef unsigned long long u64_t;

// ---- scratch (device globals; no runtime allocation) ----
__device__ float g_w[B_*COUT*WPB];
__device__ float g_bias[B_*COUT];
__device__ float g_y[YTOT];             // pre-upsample activations (16.4 MB)
__device__ float g_sum[COUT];
__device__ float g_sumsq[COUT];
__device__ float g_scale[COUT];
__device__ float g_shift[COUT];

// ---- packed fp32x2 helpers (Blackwell FFMA2 via PTX) ----
__device__ __forceinline__ u64_t pk2(float v) {
    u64_t r; asm("mov.b64 %0, {%1,%1};" : "=l"(r) : "f"(v)); return r;
}
__device__ __forceinline__ void ffma2(u64_t& d, u64_t a, u64_t b) {
    asm("fma.rn.f32x2 %0, %1, %2, %0;" : "+l"(d) : "l"(a), "l"(b));
}
__device__ __forceinline__ float lo32(u64_t v) { return __uint_as_float((unsigned)v); }
__device__ __forceinline__ float hi32(u64_t v) { return __uint_as_float((unsigned)(v >> 32)); }

// ---------------------------------------------------------------------------
// Kernel 1: routing + combined weights/bias, zero stat accumulators
// ---------------------------------------------------------------------------
__global__ void k_route(const float* __restrict__ emb,
                        const float* __restrict__ rw,
                        const float* __restrict__ rb,
                        const float* __restrict__ ek,
                        const float* __restrict__ eb) {
    float r[B_][E_];
    #pragma unroll
    for (int b = 0; b < B_; b++)
        #pragma unroll
        for (int e = 0; e < E_; e++) {
            float t = fmaf(emb[b], rw[e], rb[e]);
            r[b][e] = 1.0f / (1.0f + expf(-t));
        }

    int idx = blockIdx.x * blockDim.x + threadIdx.x;
    const int W = COUT * CIN * 27;
    if (idx < B_ * W) {
        int b = idx / W;
        int w = idx - b * W;
        float s = 0.0f;
        #pragma unroll
        for (int e = 0; e < E_; e++) s = fmaf(r[b][e], ek[e * W + w], s);
        g_w[idx] = s;
    }
    if (idx < B_ * COUT) {
        int b = idx / COUT, o = idx - b * COUT;
        float s = 0.0f;
        #pragma unroll
        for (int e = 0; e < E_; e++) s = fmaf(r[b][e], eb[e * COUT + o], s);
        g_bias[idx] = s;
    }
    if (idx < COUT) { g_sum[idx] = 0.0f; g_sumsq[idx] = 0.0f; }
}

// ---------------------------------------------------------------------------
// Kernel 2: direct 3x3x3 conv + bias + BN stats.
//   - cp.async double-buffered input slab (row-per-thread loader, zfill halo)
//   - packed fp32x2 FMA: even-pair accA (kx=0,2) + odd-phase accB (kx=1)
// grid = (10, 32, 2), block = 256 (threads 0..199 compute, 0..251 load)
// ---------------------------------------------------------------------------
__global__ void __launch_bounds__(256, 2)
k_conv(const float* __restrict__ x) {
    extern __shared__ float dyn[];
    float* sh  = dyn;                    // [2][SLABVOL]
    float* wsh = dyn + 2 * SLABVOL;      // [WPB]
    float* red = wsh + WPB;              // [16]

    const int zt = blockIdx.x;
    const int oc = blockIdx.y;
    const int b  = blockIdx.z;
    const int t  = threadIdx.x;
    const int z0 = zt * TZ;

    // weights for this (b, oc)
    for (int i = t; i < WPB; i += 256)
        wsh[i] = g_w[(b * COUT + oc) * WPB + i];

    // ---- loader setup: one smem row (42 floats) per thread, t < 252 ----
    const float* xb = x + (size_t)(b * CIN) * SP;
    const bool isload = (t < 252);
    const int lz = t / 42, ly = t - 42 * (t / 42);
    const int gz = z0 - 1 + lz, gy = ly - 1;
    const bool rowok = isload && ((unsigned)gz < D_) && ((unsigned)gy < D_);
    const long gofs = (long)gz * 1600 + (long)gy * 40 - 1;
    const unsigned sdst0 = (unsigned)__cvta_generic_to_shared(sh) + (unsigned)(t * SY * 4);

    auto prefetch = [&](int ic, int buf) {
        if (!isload) return;
        const float* src = xb + (size_t)ic * SP + gofs;
        unsigned d = sdst0 + (unsigned)buf * (SLABVOL * 4);
        #pragma unroll
        for (int xx = 0; xx < SY; xx++) {
            bool ok = rowok && ((unsigned)(xx - 1) < D_);
            const float* s = ok ? (src + xx) : xb;
            int sz = ok ? 4 : 0;
            asm volatile("cp.async.ca.shared.global [%0], [%1], 4, %2;"
                         :: "r"(d + xx * 4), "l"(s), "r"(sz));
        }
    };

    // ---- compute setup ----
    const int ty = t / 5;                 // 0..39
    const int xs = (t % 5) * 8;           // 0,8,16,24,32
    const bool active = (t < 200);

    u64_t accA[TZ][4];
    u64_t accB[TZ][3];
    float accS0[TZ], accS7[TZ];
    #pragma unroll
    for (int z = 0; z < TZ; z++) {
        #pragma unroll
        for (int j = 0; j < 4; j++) accA[z][j] = 0ull;
        #pragma unroll
        for (int j = 0; j < 3; j++) accB[z][j] = 0ull;
        accS0[z] = 0.0f; accS7[z] = 0.0f;
    }

    // prologue: fill buffer 0 with ic=0
    prefetch(0, 0);
    asm volatile("cp.async.commit_group;");

    for (int ic = 0; ic < CIN; ic++) {
        __syncthreads();   // target buffer of next prefetch is no longer being read
        if (ic + 1 < CIN) prefetch(ic + 1, (ic + 1) & 1);
        asm volatile("cp.async.commit_group;");
        asm volatile("cp.async.wait_group 1;");   // buffer (ic&1) is ready
        __syncthreads();

        if (active) {
            const float* S  = sh + (ic & 1) * SLABVOL;
            const float* wv = wsh + ic * 27;
            #pragma unroll 1
            for (int ky = 0; ky < 3; ky++) {
                u64_t wp0[3], wp1[3], wp2[3];
                float w1s[3];
                #pragma unroll
                for (int dz = 0; dz < 3; dz++) {
                    float a0 = wv[dz * 9 + ky * 3 + 0];
                    float a1 = wv[dz * 9 + ky * 3 + 1];
                    float a2 = wv[dz * 9 + ky * 3 + 2];
                    wp0[dz] = pk2(a0); wp1[dz] = pk2(a1); wp2[dz] = pk2(a2);
                    w1s[dz] = a1;
                }
                #pragma unroll
                for (int zz = 0; zz < SLABZ; zz++) {
                    const float* rowp = S + (zz * SY + ty + ky) * SY + xs;  // 8B aligned
                    u64_t rp[5];
                    #pragma unroll
                    for (int i = 0; i < 5; i++)
                        rp[i] = *(const u64_t*)(rowp + 2 * i);
                    #pragma unroll
                    for (int dz = 0; dz < 3; dz++) {
                        const int z = zz - dz;
                        if (z >= 0 && z < TZ) {        // compile-time after unroll
                            #pragma unroll
                            for (int j = 0; j < 4; j++) ffma2(accA[z][j], rp[j],     wp0[dz]);
                            #pragma unroll
                            for (int j = 0; j < 4; j++) ffma2(accA[z][j], rp[j + 1], wp2[dz]);
                            #pragma unroll
                            for (int j = 0; j < 3; j++) ffma2(accB[z][j], rp[j + 1], wp1[dz]);
                            accS0[z] = fmaf(w1s[dz], hi32(rp[0]), accS0[z]);  // out0 += w1*r[1]
                            accS7[z] = fmaf(w1s[dz], lo32(rp[4]), accS7[z]);  // out7 += w1*r[8]
                        }
                    }
                }
            }
        }
    }

    // ---- epilogue: merge pairings, bias, store y, BN partial sums ----
    float s1 = 0.0f, s2 = 0.0f;
    if (active) {
        const float bias = g_bias[b * COUT + oc];
        float* yp = g_y + (size_t)(b * COUT + oc) * SP + z0 * 1600 + ty * 40 + xs;
        #pragma unroll
        for (int z = 0; z < TZ; z++) {
            float o[8];
            o[0] = lo32(accA[z][0]) + accS0[z];
            o[1] = hi32(accA[z][0]) + lo32(accB[z][0]);
            o[2] = lo32(accA[z][1]) + hi32(accB[z][0]);
            o[3] = hi32(accA[z][1]) + lo32(accB[z][1]);
            o[4] = lo32(accA[z][2]) + hi32(accB[z][1]);
            o[5] = hi32(accA[z][2]) + lo32(accB[z][2]);
            o[6] = lo32(accA[z][3]) + hi32(accB[z][2]);
            o[7] = hi32(accA[z][3]) + accS7[z];
            float4 q0, q1;
            float v;
            v = o[0] + bias; s1 += v; s2 = fmaf(v, v, s2); q0.x = v;
            v = o[1] + bias; s1 += v; s2 = fmaf(v, v, s2); q0.y = v;
            v = o[2] + bias; s1 += v; s2 = fmaf(v, v, s2); q0.z = v;
            v = o[3] + bias; s1 += v; s2 = fmaf(v, v, s2); q0.w = v;
            v = o[4] + bias; s1 += v; s2 = fmaf(v, v, s2); q1.x = v;
            v = o[5] + bias; s1 += v; s2 = fmaf(v, v, s2); q1.y = v;
            v = o[6] + bias; s1 += v; s2 = fmaf(v, v, s2); q1.z = v;
            v = o[7] + bias; s1 += v; s2 = fmaf(v, v, s2); q1.w = v;
            *(float4*)(yp + z * 1600)     = q0;   // xs multiple of 8 -> 32B aligned
            *(float4*)(yp + z * 1600 + 4) = q1;
        }
    }
    // block reduction -> atomic per-channel stats
    #pragma unroll
    for (int o = 16; o > 0; o >>= 1) {
        s1 += __shfl_down_sync(0xffffffff, s1, o);
        s2 += __shfl_down_sync(0xffffffff, s2, o);
    }
    const int wid = t >> 5, lane = t & 31;
    __syncthreads();
    if (lane == 0) { red[wid] = s1; red[8 + wid] = s2; }
    __syncthreads();
    if (t == 0) {
        float a = 0.0f, q = 0.0f;
        #pragma unroll
        for (int i = 0; i < 8; i++) { a += red[i]; q += red[8 + i]; }
        atomicAdd(&g_sum[oc], a);
        atomicAdd(&g_sumsq[oc], q);
    }
}

// ---------------------------------------------------------------------------
// Kernel 3: finalize BN -> per-channel scale/shift
// ---------------------------------------------------------------------------
__global__ void k_stats(const float* __restrict__ gamma,
                        const float* __restrict__ beta) {
    int c = threadIdx.x;
    if (c < COUT) {
        const float n = (float)(B_ * SP);
        float mean = g_sum[c] / n;
        float var  = g_sumsq[c] / n - mean * mean;
        float sc = gamma[c] * rsqrtf(var + 1e-5f);
        g_scale[c] = sc;
        g_shift[c] = beta[c] - mean * sc;
    }
}

// ---------------------------------------------------------------------------
// Kernel 4: affine + LeakyReLU + nearest upsample x2; float2 in, 4x float4 out
// ---------------------------------------------------------------------------
__global__ void __launch_bounds__(256)
k_up(float* __restrict__ out) {
    int idx = blockIdx.x * blockDim.x + threadIdx.x;  // over YTOT/2
    if (idx >= YTOT / 2) return;
    int i2 = idx * 2;
    int xw = i2 % 40;                 // even
    int rest = i2 / 40;
    int yw = rest % 40; rest /= 40;
    int zw = rest % 40; rest /= 40;
    int c  = rest % COUT;
    int b  = rest / COUT;

    float2 v = *(const float2*)&g_y[i2];
    float sc = g_scale[c], sf = g_shift[c];
    float a0 = fmaf(sc, v.x, sf); a0 = (a0 >= 0.0f) ? a0 : 0.1f * a0;
    float a1 = fmaf(sc, v.y, sf); a1 = (a1 >= 0.0f) ? a1 : 0.1f * a1;
    float4 p = make_float4(a0, a0, a1, a1);

    size_t base = ((size_t)(b * COUT + c) * 512000u)
                + (size_t)(2 * zw) * 6400u + (size_t)(2 * yw) * 80u + (size_t)(2 * xw);
    float4* o4 = (float4*)(out + base);       // 16B aligned (2*xw % 4 == 0)
    o4[0]    = p;    // (2z,   2y  )
    o4[20]   = p;    // (2z,   2y+1)   +80 floats
    o4[1600] = p;    // (2z+1, 2y  )   +6400 floats
    o4[1620] = p;    // (2z+1, 2y+1)
}

// ---------------------------------------------------------------------------
extern "C" void kernel_launch(void* const* d_in, const int* in_sizes, int n_in,
                              void* d_out, int out_size) {
    const float* x     = (const float*)d_in[0];
    const float* emb   = (const float*)d_in[1];
    const float* rw    = (const float*)d_in[2];
    const float* rb    = (const float*)d_in[3];
    const float* ek    = (const float*)d_in[4];
    const float* eb    = (const float*)d_in[5];
    const float* gamma = (const float*)d_in[6];
    const float* beta  = (const float*)d_in[7];
    float* out = (float*)d_out;

    k_route<<<(B_ * COUT * CIN * 27 + 255) / 256, 256>>>(emb, rw, rb, ek, eb);

    static int smem_set = 0;
    size_t shbytes = (size_t)(2 * SLABVOL + WPB + 16) * sizeof(float);  // ~88.2 KB
    if (!smem_set) {
        cudaFuncSetAttribute(k_conv, cudaFuncAttributeMaxDynamicSharedMemorySize, (int)shbytes);
        smem_set = 1;
    }
    dim3 gconv(NZT, COUT, B_);
    k_conv<<<gconv, 256, shbytes>>>(x);

    k_stats<<<1, 32>>>(gamma, beta);

    k_up<<<(YTOT / 2 + 255) / 256, 256>>>(out);
}